// round 6
// baseline (speedup 1.0000x reference)
#include <cuda_runtime.h>
#include <math.h>

// Problem constants (fixed shapes per reference)
#define CN 100000      // nodes
#define CE 1600000     // edges
#define CG 4096        // graphs
#define CH 128         // hidden
#define CF 32          // input features
#define NB_SCAN 98     // ceil(CN/1024)
#define ASTR 132       // float stride of smem A-tile rows (k-major)

// ---------------- device scratch (static, no allocation) ----------------
__device__ __align__(16) int   g_deg[CN];
__device__ __align__(16) int   g_rowptr[CN];
__device__ __align__(16) int   g_cursor[CN];
__device__ __align__(16) int2  g_colw[CE];       // (src, weight-as-int) per edge
__device__ __align__(16) float g_dinv[CN];
__device__ __align__(16) float g_bufA[(size_t)CN * CH];
__device__ __align__(16) float g_bufB[(size_t)CN * CH];
__device__ __align__(16) float g_sums[6 * CH];   // (sum, sumsq) x 3 layers
__device__ __align__(16) int   g_bsums[128];

// ---------------- packed fp32x2 helpers ----------------
__device__ __forceinline__ unsigned long long pack2(float lo, float hi) {
    unsigned long long r;
    asm("mov.b64 %0, {%1, %2};" : "=l"(r) : "f"(lo), "f"(hi));
    return r;
}
__device__ __forceinline__ void unpack2(unsigned long long v, float& lo, float& hi) {
    asm("mov.b64 {%0, %1}, %2;" : "=f"(lo), "=f"(hi) : "l"(v));
}
__device__ __forceinline__ void ffma2(unsigned long long& d, unsigned long long a,
                                      unsigned long long b) {
    asm("fma.rn.f32x2 %0, %1, %2, %0;" : "+l"(d) : "l"(a), "l"(b));
}

__device__ __forceinline__ float4 bnrelu4(float4 v, float4 sc, float4 sh) {
    float4 r;
    r.x = fmaxf(fmaf(sc.x, v.x, sh.x), 0.f);
    r.y = fmaxf(fmaf(sc.y, v.y, sh.y), 0.f);
    r.z = fmaxf(fmaf(sc.z, v.z, sh.z), 0.f);
    r.w = fmaxf(fmaf(sc.w, v.w, sh.w), 0.f);
    return r;
}

// ---------------- CSR build (edge_index is int32) ----------------
__global__ void k_deg(const int* __restrict__ ei) {
    int e = blockIdx.x * blockDim.x + threadIdx.x;
    if (e < CE) atomicAdd(&g_deg[ei[CE + e]], 1);
}

__global__ void k_scan1() {     // block scan; also dinv + cursor zero
    __shared__ int s[1024];
    int tid = threadIdx.x;
    int i = blockIdx.x * 1024 + tid;
    int v = (i < CN) ? g_deg[i] : 0;
    if (i < CN) {
        g_dinv[i] = rsqrtf((float)(v + 1));   // +1 self loop
        g_cursor[i] = 0;
    }
    s[tid] = v;
    __syncthreads();
    for (int off = 1; off < 1024; off <<= 1) {
        int t = (tid >= off) ? s[tid - off] : 0;
        __syncthreads();
        s[tid] += t;
        __syncthreads();
    }
    if (i < CN) g_rowptr[i] = s[tid] - v;   // exclusive within block
    if (tid == 1023) g_bsums[blockIdx.x] = s[1023];
}

// merged scan2+scan3: each 256-thread block scans the 98 block sums in smem,
// then applies the fixup. Arrays sized to blockDim (256) — positions <128 of a
// Hillis-Steele scan depend only on lower positions, and only sx[0..97] is used.
__global__ void k_scanfix() {
    __shared__ int s[256];
    __shared__ int sx[256];
    int tid = threadIdx.x;
    int v = (tid < NB_SCAN) ? g_bsums[tid] : 0;
    s[tid] = v;
    __syncthreads();
    for (int off = 1; off < 128; off <<= 1) {
        int t = (tid >= off) ? s[tid - off] : 0;
        __syncthreads();
        s[tid] += t;
        __syncthreads();
    }
    sx[tid] = s[tid] - v;   // exclusive
    __syncthreads();
    int i = blockIdx.x * blockDim.x + tid;
    if (i < CN) g_rowptr[i] += sx[i >> 10];
    if (blockIdx.x == 0)
        for (int j = tid; j < 6 * CH; j += blockDim.x) g_sums[j] = 0.f;
}

// scatter edge -> (src, w) with w = dinv[src]*dinv[dst] precomputed
__global__ void k_scatter(const int* __restrict__ ei) {
    int e = blockIdx.x * blockDim.x + threadIdx.x;
    if (e < CE) {
        int s = ei[e];
        int d = ei[CE + e];
        int p = atomicAdd(&g_cursor[d], 1);
        float w = g_dinv[s] * g_dinv[d];
        g_colw[g_rowptr[d] + p] = make_int2(s, __float_as_int(w));
    }
}

// ---------------- fused layer 0: aggregate (F=32) + GEMM K=32 -> bufB + stats ----
__global__ void __launch_bounds__(256, 2) k_l0fused(const float* __restrict__ x,
                                                    const float* __restrict__ W,
                                                    const float* __restrict__ bias,
                                                    float* __restrict__ out,
                                                    float* __restrict__ sums) {
    extern __shared__ float sm[];
    float* Ws = sm;                     // [32][128]
    float* As = sm + 32 * 128;          // [32][ASTR] k-major
    int tid = threadIdx.x;
    int tx = tid & 15;
    int ty = tid >> 4;
    int wid = tid >> 5;
    int lane = tid & 31;
    int row0 = blockIdx.x * 128;

    for (int i = tid; i < 32 * 128; i += 256) Ws[i] = W[i];

    // aggregate 16 nodes per warp; lane = feature
    for (int n = 0; n < 16; n++) {
        int r = wid * 16 + n;
        int node = row0 + r;
        float acc = 0.f;
        if (node < CN) {
            float dv = g_dinv[node];
            acc = dv * dv * x[(size_t)node * CF + lane];   // self loop
            int e = g_rowptr[node];
            int e1 = e + g_deg[node];
            for (; e + 1 < e1; e += 2) {
                int2 c0 = g_colw[e], c1 = g_colw[e + 1];
                float u0 = x[(size_t)c0.x * CF + lane];
                float u1 = x[(size_t)c1.x * CF + lane];
                acc = fmaf(__int_as_float(c0.y), u0, acc);
                acc = fmaf(__int_as_float(c1.y), u1, acc);
            }
            if (e < e1) {
                int2 c = g_colw[e];
                acc = fmaf(__int_as_float(c.y), x[(size_t)c.x * CF + lane], acc);
            }
        }
        As[lane * ASTR + r] = acc;
    }
    __syncthreads();

    // GEMM K=32: row-pair FFMA2 (A pairs free from k-major smem, B duplicated via MOV)
    unsigned long long acc[4][8];  // 4 row-pairs x 8 cols
#pragma unroll
    for (int p = 0; p < 4; p++)
#pragma unroll
        for (int j = 0; j < 8; j++) acc[p][j] = 0ull;

#pragma unroll
    for (int k = 0; k < 32; k++) {
        const ulonglong2* Arow = (const ulonglong2*)&As[k * ASTR + ty * 8];
        ulonglong2 a01 = Arow[0];
        ulonglong2 a23 = Arow[1];
        unsigned long long ap[4] = {a01.x, a01.y, a23.x, a23.y};
        float4 b0 = *(const float4*)&Ws[k * 128 + tx * 8];
        float4 b1 = *(const float4*)&Ws[k * 128 + tx * 8 + 4];
        unsigned long long bp[8] = {
            pack2(b0.x, b0.x), pack2(b0.y, b0.y), pack2(b0.z, b0.z), pack2(b0.w, b0.w),
            pack2(b1.x, b1.x), pack2(b1.y, b1.y), pack2(b1.z, b1.z), pack2(b1.w, b1.w)};
#pragma unroll
        for (int p = 0; p < 4; p++)
#pragma unroll
            for (int j = 0; j < 8; j++) ffma2(acc[p][j], ap[p], bp[j]);
    }

    // epilogue: + bias, store, per-column partial stats
    float4 bj0 = *(const float4*)&bias[tx * 8];
    float4 bj1 = *(const float4*)&bias[tx * 8 + 4];
    float bj[8] = {bj0.x, bj0.y, bj0.z, bj0.w, bj1.x, bj1.y, bj1.z, bj1.w};
    float csum[8], csq[8];
#pragma unroll
    for (int j = 0; j < 8; j++) { csum[j] = 0.f; csq[j] = 0.f; }
#pragma unroll
    for (int p = 0; p < 4; p++) {
        float vlo[8], vhi[8];
#pragma unroll
        for (int j = 0; j < 8; j++) unpack2(acc[p][j], vlo[j], vhi[j]);
        int r = row0 + ty * 8 + 2 * p;
        if (r < CN) {
#pragma unroll
            for (int j = 0; j < 8; j++) { vlo[j] += bj[j]; csum[j] += vlo[j]; csq[j] += vlo[j] * vlo[j]; }
            float* orow = out + (size_t)r * 128 + tx * 8;
            *(float4*)&orow[0] = make_float4(vlo[0], vlo[1], vlo[2], vlo[3]);
            *(float4*)&orow[4] = make_float4(vlo[4], vlo[5], vlo[6], vlo[7]);
        }
        if (r + 1 < CN) {
#pragma unroll
            for (int j = 0; j < 8; j++) { vhi[j] += bj[j]; csum[j] += vhi[j]; csq[j] += vhi[j] * vhi[j]; }
            float* orow = out + (size_t)(r + 1) * 128 + tx * 8;
            *(float4*)&orow[0] = make_float4(vhi[0], vhi[1], vhi[2], vhi[3]);
            *(float4*)&orow[4] = make_float4(vhi[4], vhi[5], vhi[6], vhi[7]);
        }
    }
    __syncthreads();
    float* red = sm;
#pragma unroll
    for (int j = 0; j < 8; j++) red[ty * 128 + tx * 8 + j] = csum[j];
    __syncthreads();
    if (tid < 128) {
        float t = 0.f;
#pragma unroll
        for (int q = 0; q < 16; q++) t += red[q * 128 + tid];
        atomicAdd(&sums[tid], t);
    }
    __syncthreads();
#pragma unroll
    for (int j = 0; j < 8; j++) red[ty * 128 + tx * 8 + j] = csq[j];
    __syncthreads();
    if (tid < 128) {
        float t = 0.f;
#pragma unroll
        for (int q = 0; q < 16; q++) t += red[q * 128 + tid];
        atomicAdd(&sums[128 + tid], t);
    }
}

// ---------------- agg layers 1/2: BN params computed in-block from sums ----------
__global__ void __launch_bounds__(256) k_agg128(const float* __restrict__ xin,
                                                const float* __restrict__ sums,
                                                const float* __restrict__ gamma,
                                                const float* __restrict__ beta,
                                                float* __restrict__ out) {
    __shared__ float4 s_sc4[32], s_sh4[32];
    int tid = threadIdx.x;
    if (tid < 128) {
        float mean = sums[tid] * (1.f / CN);
        float var = sums[128 + tid] * (1.f / CN) - mean * mean;
        float sc = gamma[tid] * rsqrtf(var + 1e-5f);
        ((float*)s_sc4)[tid] = sc;
        ((float*)s_sh4)[tid] = fmaf(-mean, sc, beta[tid]);
    }
    __syncthreads();

    int warp = (blockIdx.x * blockDim.x + tid) >> 5;
    if (warp >= CN) return;
    int lane = tid & 31;
    float4 sc = s_sc4[lane];
    float4 sh = s_sh4[lane];
    float dv = g_dinv[warp];
    float4 v = ((const float4*)(xin + (size_t)warp * CH))[lane];
    v = bnrelu4(v, sc, sh);
    float dv2 = dv * dv;
    float4 acc = make_float4(dv2 * v.x, dv2 * v.y, dv2 * v.z, dv2 * v.w);
    int e = g_rowptr[warp];
    int e1 = e + g_deg[warp];
    for (; e + 1 < e1; e += 2) {
        int2 c0 = g_colw[e], c1 = g_colw[e + 1];
        float w0 = __int_as_float(c0.y), w1 = __int_as_float(c1.y);
        float4 u0 = ((const float4*)(xin + (size_t)c0.x * CH))[lane];
        float4 u1 = ((const float4*)(xin + (size_t)c1.x * CH))[lane];
        u0 = bnrelu4(u0, sc, sh);
        u1 = bnrelu4(u1, sc, sh);
        acc.x = fmaf(w0, u0.x, acc.x); acc.y = fmaf(w0, u0.y, acc.y);
        acc.z = fmaf(w0, u0.z, acc.z); acc.w = fmaf(w0, u0.w, acc.w);
        acc.x = fmaf(w1, u1.x, acc.x); acc.y = fmaf(w1, u1.y, acc.y);
        acc.z = fmaf(w1, u1.z, acc.z); acc.w = fmaf(w1, u1.w, acc.w);
    }
    if (e < e1) {
        int2 c = g_colw[e];
        float w = __int_as_float(c.y);
        float4 u = ((const float4*)(xin + (size_t)c.x * CH))[lane];
        u = bnrelu4(u, sc, sh);
        acc.x = fmaf(w, u.x, acc.x); acc.y = fmaf(w, u.y, acc.y);
        acc.z = fmaf(w, u.z, acc.z); acc.w = fmaf(w, u.w, acc.w);
    }
    ((float4*)(out + (size_t)warp * CH))[lane] = acc;
}

// ---------------- GEMM K=128: out = A @ W + bias, fused BN stats ----------------
__global__ void __launch_bounds__(256, 2) k_gemm128(const float* __restrict__ A,
                                                    const float* __restrict__ W,
                                                    const float* __restrict__ bias,
                                                    float* __restrict__ out,
                                                    float* __restrict__ sums) {
    extern __shared__ float sm[];
    float* Ws = sm;                  // [128][128]
    float* As = sm + 128 * 128;      // [32][ASTR] k-major chunk
    int tid = threadIdx.x;
    int tx = tid & 15;
    int ty = tid >> 4;
    int row0 = blockIdx.x * 128;

    for (int i = tid; i < 128 * 128; i += 256) Ws[i] = W[i];

    unsigned long long acc[4][8];  // 4 row-pairs x 8 cols
#pragma unroll
    for (int p = 0; p < 4; p++)
#pragma unroll
        for (int j = 0; j < 8; j++) acc[p][j] = 0ull;

    for (int kc = 0; kc < 128; kc += 32) {
        __syncthreads();
        for (int i = tid; i < 128 * 32; i += 256) {
            int r = i >> 5, k = i & 31;
            int gr = row0 + r;
            float v = (gr < CN) ? A[(size_t)gr * 128 + kc + k] : 0.f;
            As[k * ASTR + r] = v;
        }
        __syncthreads();
#pragma unroll
        for (int k = 0; k < 32; k++) {
            const ulonglong2* Arow = (const ulonglong2*)&As[k * ASTR + ty * 8];
            ulonglong2 a01 = Arow[0];
            ulonglong2 a23 = Arow[1];
            unsigned long long ap[4] = {a01.x, a01.y, a23.x, a23.y};
            float4 b0 = *(const float4*)&Ws[(kc + k) * 128 + tx * 8];
            float4 b1 = *(const float4*)&Ws[(kc + k) * 128 + tx * 8 + 4];
            unsigned long long bp[8] = {
                pack2(b0.x, b0.x), pack2(b0.y, b0.y), pack2(b0.z, b0.z), pack2(b0.w, b0.w),
                pack2(b1.x, b1.x), pack2(b1.y, b1.y), pack2(b1.z, b1.z), pack2(b1.w, b1.w)};
#pragma unroll
            for (int p = 0; p < 4; p++)
#pragma unroll
                for (int j = 0; j < 8; j++) ffma2(acc[p][j], ap[p], bp[j]);
        }
    }

    float4 bj0 = *(const float4*)&bias[tx * 8];
    float4 bj1 = *(const float4*)&bias[tx * 8 + 4];
    float bj[8] = {bj0.x, bj0.y, bj0.z, bj0.w, bj1.x, bj1.y, bj1.z, bj1.w};
    float csum[8], csq[8];
#pragma unroll
    for (int j = 0; j < 8; j++) { csum[j] = 0.f; csq[j] = 0.f; }
#pragma unroll
    for (int p = 0; p < 4; p++) {
        float vlo[8], vhi[8];
#pragma unroll
        for (int j = 0; j < 8; j++) unpack2(acc[p][j], vlo[j], vhi[j]);
        int r = row0 + ty * 8 + 2 * p;
        if (r < CN) {
#pragma unroll
            for (int j = 0; j < 8; j++) { vlo[j] += bj[j]; csum[j] += vlo[j]; csq[j] += vlo[j] * vlo[j]; }
            float* orow = out + (size_t)r * 128 + tx * 8;
            *(float4*)&orow[0] = make_float4(vlo[0], vlo[1], vlo[2], vlo[3]);
            *(float4*)&orow[4] = make_float4(vlo[4], vlo[5], vlo[6], vlo[7]);
        }
        if (r + 1 < CN) {
#pragma unroll
            for (int j = 0; j < 8; j++) { vhi[j] += bj[j]; csum[j] += vhi[j]; csq[j] += vhi[j] * vhi[j]; }
            float* orow = out + (size_t)(r + 1) * 128 + tx * 8;
            *(float4*)&orow[0] = make_float4(vhi[0], vhi[1], vhi[2], vhi[3]);
            *(float4*)&orow[4] = make_float4(vhi[4], vhi[5], vhi[6], vhi[7]);
        }
    }
    __syncthreads();
    float* red = sm;
#pragma unroll
    for (int j = 0; j < 8; j++) red[ty * 128 + tx * 8 + j] = csum[j];
    __syncthreads();
    if (tid < 128) {
        float t = 0.f;
#pragma unroll
        for (int q = 0; q < 16; q++) t += red[q * 128 + tid];
        atomicAdd(&sums[tid], t);
    }
    __syncthreads();
#pragma unroll
    for (int j = 0; j < 8; j++) red[ty * 128 + tx * 8 + j] = csq[j];
    __syncthreads();
    if (tid < 128) {
        float t = 0.f;
#pragma unroll
        for (int q = 0; q < 16; q++) t += red[q * 128 + tid];
        atomicAdd(&sums[128 + tid], t);
    }
}

// ---------------- fused pooling + MLP head (batch sorted; BN in-block) ----------
__global__ void __launch_bounds__(128) k_poolhead(const int* __restrict__ batch,
                                                  const float* __restrict__ sums,
                                                  const float* __restrict__ gamma,
                                                  const float* __restrict__ beta,
                                                  const float* __restrict__ Wh1,
                                                  const float* __restrict__ bh1,
                                                  const float* __restrict__ Wh2,
                                                  const float* __restrict__ bh2,
                                                  float* __restrict__ out) {
    __shared__ float row[128];
    __shared__ float red[64];
    int g = blockIdx.x;
    int t = threadIdx.x;  // 128 threads

    float mean = sums[t] * (1.f / CN);
    float var = sums[128 + t] * (1.f / CN) - mean * mean;
    float sc = gamma[t] * rsqrtf(var + 1e-5f);
    float sh = fmaf(-mean, sc, beta[t]);

    int lo = 0, hi = CN;
    while (lo < hi) { int m = (lo + hi) >> 1; if (batch[m] < g) lo = m + 1; else hi = m; }
    int start = lo;
    hi = CN;
    while (lo < hi) { int m = (lo + hi) >> 1; if (batch[m] < g + 1) lo = m + 1; else hi = m; }
    int end = lo;

    float acc = 0.f;
    for (int i = start; i < end; i++)
        acc += fmaxf(fmaf(sc, g_bufB[(size_t)i * CH + t], sh), 0.f);
    float inv = 1.f / fmaxf((float)(end - start), 1.f);
    row[t] = acc * inv;
    __syncthreads();

    if (t < 64) {
        float a = bh1[t];
#pragma unroll 8
        for (int f = 0; f < 128; f++) a = fmaf(row[f], Wh1[f * 64 + t], a);
        a = fmaxf(a, 0.f);
        red[t] = a * Wh2[t];
    }
    __syncthreads();
    if (t < 32) {
        float v = red[t] + red[t + 32];
#pragma unroll
        for (int off = 16; off > 0; off >>= 1)
            v += __shfl_down_sync(0xffffffffu, v, off);
        if (t == 0) out[g] = v + bh2[0];
    }
}

// ---------------- launch ----------------
extern "C" void kernel_launch(void* const* d_in, const int* in_sizes, int n_in,
                              void* d_out, int out_size) {
    const float* x  = (const float*)d_in[0];
    const int* ei   = (const int*)d_in[1];     // int32 (JAX x64 disabled)
    const int* batch= (const int*)d_in[2];     // int32
    const float* W0 = (const float*)d_in[3];
    const float* b0 = (const float*)d_in[4];
    const float* g0 = (const float*)d_in[5];
    const float* be0= (const float*)d_in[6];
    const float* W1 = (const float*)d_in[7];
    const float* b1 = (const float*)d_in[8];
    const float* g1 = (const float*)d_in[9];
    const float* be1= (const float*)d_in[10];
    const float* W2 = (const float*)d_in[11];
    const float* b2 = (const float*)d_in[12];
    const float* g2 = (const float*)d_in[13];
    const float* be2= (const float*)d_in[14];
    const float* Wh1= (const float*)d_in[15];
    const float* bh1= (const float*)d_in[16];
    const float* Wh2= (const float*)d_in[17];
    const float* bh2= (const float*)d_in[18];
    float* out = (float*)d_out;

    void* p;
    cudaGetSymbolAddress(&p, g_deg);    int*   degp  = (int*)p;
    cudaGetSymbolAddress(&p, g_bufA);   float* bufA  = (float*)p;
    cudaGetSymbolAddress(&p, g_bufB);   float* bufB  = (float*)p;
    cudaGetSymbolAddress(&p, g_sums);   float* sums  = (float*)p;

    const int SMG = 128 * 128 * 4 + 32 * ASTR * 4;   // 82432 B
    const int SM0 = 32 * 128 * 4 + 32 * ASTR * 4;    // 33280 B
    cudaFuncSetAttribute(k_gemm128, cudaFuncAttributeMaxDynamicSharedMemorySize, SMG);
    cudaFuncSetAttribute(k_l0fused, cudaFuncAttributeMaxDynamicSharedMemorySize, SM0);

    const int gemmBlocks = (CN + 127) / 128;   // 782
    const int aggBlocks = (CN + 7) / 8;        // 12500

    cudaMemsetAsync(degp, 0, CN * sizeof(int));
    k_deg<<<(CE + 255) / 256, 256>>>(ei);
    k_scan1<<<NB_SCAN, 1024>>>();
    k_scanfix<<<(CN + 255) / 256, 256>>>();
    k_scatter<<<(CE + 255) / 256, 256>>>(ei);

    // Layer 0 fused: aggregate + GEMM -> bufB (pre-BN h0) + stats
    k_l0fused<<<gemmBlocks, 256, SM0>>>(x, W0, b0, bufB, sums);

    // Layer 1
    k_agg128<<<aggBlocks, 256>>>(bufB, sums, g0, be0, bufA);
    k_gemm128<<<gemmBlocks, 256, SMG>>>(bufA, W1, b1, bufB, sums + 256);

    // Layer 2
    k_agg128<<<aggBlocks, 256>>>(bufB, sums + 256, g1, be1, bufA);
    k_gemm128<<<gemmBlocks, 256, SMG>>>(bufA, W2, b2, bufB, sums + 512);

    // Fused pool + head
    k_poolhead<<<CG, 128>>>(batch, sums + 512, g2, be2, Wh1, bh1, Wh2, bh2, out);
}